// round 9
// baseline (speedup 1.0000x reference)
#include <cuda_runtime.h>

// ROICrop: bilinear crop of 1024 ROIs from (4,256,200,304) fp32 source into
// (1024,256,14,14) fp32 output. KEEP_AR (AR=1) + 10% extend ROI adjustment.
//
// R9: R4/R8 both sit on the l1tex wavefront-rate wall (L1 ~82-83% == computed
// wavefront cycles / duration; occupancy 61% vs 89% gave identical time).
// Two levers, both aimed at the wavefront count and the grid tail:
//
// 1) float2 tap-pair merge: o01 = o00+1 shares o00's 128B line for 31/32
//    lanes, but a second LDG.32 pays its line set again. Load float2 at
//    xe = x0 & ~1 (8B-aligned: row base y*304 is even, xe even):
//    even lanes get both x-taps from one LDG.64; odd lanes take f2.y as the
//    x0 tap and fix up x0+1 via a half-density predicated scalar load.
//    Per warp-channel: 2x4.3 + 2x~3.2 + 1.2(store) ~= 16 wf vs 18.
//    (R6's float4 version failed on the 4-wf floor + deep SEL chains; this
//    has a 2-wf floor and only 4 one-level SELs per channel.)
//    Edge cases: x0=303 (odd, clamp): fixup addr uses x1i=303 -> loads the
//    clamped tap itself, correct. x0=302 (even): f2.y = col 303 = x1i. Max
//    address 199*304+303 = 60799 < 60800.
//
// 2) C_BANDS 8 -> 16: halves the per-block wall (16-ch loop) so the grid
//    tail drops ~8% -> ~4%; band working set 15.6MB, still L2-resident.
//
// Kept: 1D grid with roi fastest-varying (wave ~= one L2-resident channel
// band of all 4 images -> source DRAM ~ one pass), pixel-per-thread,
// streaming stores.

#define SRC_C 256
#define SRC_H 200
#define SRC_W 304
#define SRC_HW (SRC_H * SRC_W)
#define OH 14
#define OW 14
#define OPIX (OH * OW)
#define C_BANDS 16
#define C_PER_BAND (SRC_C / C_BANDS)   // 16

__global__ __launch_bounds__(224, 7) void ROICrop_kernel(
    const float* __restrict__ src,
    const float* __restrict__ rois,
    float* __restrict__ out,
    int n_rois)
{
    const int bid = blockIdx.x;
    const int roi  = bid % n_rois;          // fastest-varying: wave = one band
    const int band = bid / n_rois;
    const int c0 = band * C_PER_BAND;
    const int p = threadIdx.x;
    if (p >= OPIX) return;

    const int oy = p / OW;
    const int ox = p - oy * OW;

    // ---- load + adjust ROI (redundant per-thread; broadcast loads) ----
    const float* r = rois + roi * 5;
    const int b = (int)r[0];
    float x1 = r[1], y1 = r[2], x2 = r[3], y2 = r[4];

    // keep-aspect-ratio, AR = OW/OH = 1
    {
        const float h = y2 - y1 + 1.0f;
        const float w = x2 - x1 + 1.0f;
        const float ew = (h - w) * 0.5f;     // (h*AR - w)/2 with AR=1
        if (ew > 0.0f) {
            x1 -= ew; x2 += ew;
        } else {
            const float eh = (w - h) * 0.5f; // (w/AR - h)/2
            y1 -= eh; y2 += eh;
        }
    }
    // extend ratio 0.1
    {
        const float dx = (x2 - x1 + 1.0f) * 0.05f;
        const float dy = (y2 - y1 + 1.0f) * 0.05f;
        x1 -= dx; x2 += dx;
        y1 -= dy; y2 += dy;
    }

    // ---- per-pixel sample position ----
    const float ty = (float)oy / (float)(OH - 1);
    const float tx = (float)ox / (float)(OW - 1);
    float ys = y1 + (y2 - y1) * ty;
    float xs = x1 + (x2 - x1) * tx;
    ys = fminf(fmaxf(ys, 0.0f), (float)(SRC_H - 1));
    xs = fminf(fmaxf(xs, 0.0f), (float)(SRC_W - 1));

    const float y0f = floorf(ys);
    const float x0f = floorf(xs);
    const float wy = ys - y0f;
    const float wx = xs - x0f;
    const int y0 = (int)y0f;
    const int x0 = (int)x0f;
    const int y1i = min(y0 + 1, SRC_H - 1);
    const int x1i = min(x0 + 1, SRC_W - 1);

    const float w00 = (1.0f - wy) * (1.0f - wx);
    const float w01 = (1.0f - wy) * wx;
    const float w10 = wy * (1.0f - wx);
    const float w11 = wy * wx;

    // even-aligned float2 tap addressing (all loop-invariant)
    const int xe   = x0 & ~1;               // 8B-aligned column pair
    const bool odd = (x0 & 1) != 0;
    const int rowAe = y0  * SRC_W + xe;     // float2 covers cols xe, xe+1
    const int rowBe = y1i * SRC_W + xe;
    const int o01 = y0  * SRC_W + x1i;      // odd-lane fixup (x0+1, clamped)
    const int o11 = y1i * SRC_W + x1i;

    const float* base = src + (size_t)b * SRC_C * SRC_HW + (size_t)c0 * SRC_HW;
    float* outp = out + (size_t)roi * SRC_C * OPIX + (size_t)c0 * OPIX + p;

    // ---- channel loop: 2 x LDG.64 + 2 predicated LDG.32 per channel ----
#pragma unroll 4
    for (int c = 0; c < C_PER_BAND; ++c) {
        const float* s = base + (size_t)c * SRC_HW;
        const float2 fa = __ldg((const float2*)(s + rowAe));
        const float2 fb = __ldg((const float2*)(s + rowBe));
        float ea = 0.0f, eb = 0.0f;
        if (odd) {                 // half-density predicated fixup
            ea = __ldg(s + o01);
            eb = __ldg(s + o11);
        }
        const float a0 = odd ? fa.y : fa.x;
        const float a1 = odd ? ea   : fa.y;
        const float b0 = odd ? fb.y : fb.x;
        const float b1 = odd ? eb   : fb.y;

        const float v = w00 * a0 + w01 * a1 + w10 * b0 + w11 * b1;
        __stcs(outp + (size_t)c * OPIX, v);
    }
}

extern "C" void kernel_launch(void* const* d_in, const int* in_sizes, int n_in,
                              void* d_out, int out_size)
{
    const float* src  = (const float*)d_in[0];
    const float* rois = (const float*)d_in[1];
    float* out = (float*)d_out;

    int n_rois = in_sizes[1] / 5;   // 1024
    if (n_rois < 1) n_rois = 1;
    ROICrop_kernel<<<n_rois * C_BANDS, 224>>>(src, rois, out, n_rois);
}